// round 1
// baseline (speedup 1.0000x reference)
#include <cuda_runtime.h>
#include <math.h>

#define NTOK   32768
#define BATCH  4
#define CIN    256
#define OC3    384
#define HID    128
#define NHEAD  4
#define DHEAD  32
#define SCALE  0.17677669529663687f   // 32^-0.5
#define LN_EPS 1e-5f

// ---------------- scratch (static device globals; no allocation) ----------------
__device__ __align__(16) float g_qkv[(size_t)BATCH * OC3 * NTOK];   // 201 MB
__device__ __align__(16) float g_att[(size_t)BATCH * HID * NTOK];   // 67 MB
__device__ __align__(16) float g_kmax[BATCH * NHEAD * DHEAD];
__device__ __align__(16) float g_krinv[BATCH * NHEAD * DHEAD];
__device__ __align__(16) float g_ctx[BATCH * NHEAD * DHEAD * DHEAD];

// =====================================================================
// Kernel 1: qkv[b,o,n] = sum_c w_qkv[o,c] * x[b,c,n]
// Tiled SGEMM: BM=64, BN=64, BK=16, 256 threads, 4x4 per thread.
// =====================================================================
__global__ __launch_bounds__(256) void k_qkv_gemm(const float* __restrict__ x,
                                                  const float* __restrict__ w) {
    const int b  = blockIdx.z;
    const int m0 = blockIdx.y * 64;
    const int n0 = blockIdx.x * 64;
    const int tid = threadIdx.x;
    const int tx = tid & 15, ty = tid >> 4;

    __shared__ float As[16][68];   // [k][m], padded
    __shared__ float Bs[16][64];   // [k][n]

    const float* xb = x + (size_t)b * CIN * NTOK;

    float acc[4][4];
#pragma unroll
    for (int i = 0; i < 4; i++)
#pragma unroll
        for (int j = 0; j < 4; j++) acc[i][j] = 0.f;

    const int ar = tid >> 2;          // 0..63  (A row within tile)
    const int ac = (tid & 3) << 2;    // 0,4,8,12
    const int br = tid >> 4;          // 0..15  (B row within tile)
    const int bc = (tid & 15) << 2;   // 0..60

    for (int kt = 0; kt < CIN; kt += 16) {
        float4 av = *(const float4*)&w[(size_t)(m0 + ar) * CIN + kt + ac];
        float4 bv = *(const float4*)&xb[(size_t)(kt + br) * NTOK + n0 + bc];
        As[ac + 0][ar] = av.x;
        As[ac + 1][ar] = av.y;
        As[ac + 2][ar] = av.z;
        As[ac + 3][ar] = av.w;
        *(float4*)&Bs[br][bc] = bv;
        __syncthreads();
#pragma unroll
        for (int kk = 0; kk < 16; kk++) {
            float4 a4 = *(float4*)&As[kk][ty << 2];
            float4 b4 = *(float4*)&Bs[kk][tx << 2];
            float a[4] = {a4.x, a4.y, a4.z, a4.w};
            float bb[4] = {b4.x, b4.y, b4.z, b4.w};
#pragma unroll
            for (int i = 0; i < 4; i++)
#pragma unroll
                for (int j = 0; j < 4; j++) acc[i][j] += a[i] * bb[j];
        }
        __syncthreads();
    }

    float* outp = g_qkv + ((size_t)b * OC3 + m0 + (ty << 2)) * NTOK + n0 + (tx << 2);
#pragma unroll
    for (int i = 0; i < 4; i++) {
        float4 v = make_float4(acc[i][0], acc[i][1], acc[i][2], acc[i][3]);
        *(float4*)&outp[(size_t)i * NTOK] = v;
    }
}

// =====================================================================
// Kernel 2: per-row (b,h,d) max and 1/sum(exp) for k-softmax over n.
// One block per row (512 rows).
// =====================================================================
__global__ __launch_bounds__(256) void k_kstats() {
    const int row = blockIdx.x;           // b*128 + (h*32+d)
    const int b = row >> 7, lr = row & 127;
    const float* p = g_qkv + ((size_t)b * OC3 + HID + lr) * NTOK;
    __shared__ float sred[256];
    const int tid = threadIdx.x;

    float m = -1e30f;
    for (int i = tid * 4; i < NTOK; i += 1024) {
        float4 v = *(const float4*)&p[i];
        m = fmaxf(m, fmaxf(fmaxf(v.x, v.y), fmaxf(v.z, v.w)));
    }
    sred[tid] = m;
    __syncthreads();
    for (int s = 128; s > 0; s >>= 1) {
        if (tid < s) sred[tid] = fmaxf(sred[tid], sred[tid + s]);
        __syncthreads();
    }
    m = sred[0];
    __syncthreads();

    float sum = 0.f;
    for (int i = tid * 4; i < NTOK; i += 1024) {
        float4 v = *(const float4*)&p[i];
        sum += __expf(v.x - m) + __expf(v.y - m) + __expf(v.z - m) + __expf(v.w - m);
    }
    sred[tid] = sum;
    __syncthreads();
    for (int s = 128; s > 0; s >>= 1) {
        if (tid < s) sred[tid] += sred[tid + s];
        __syncthreads();
    }
    if (tid == 0) {
        g_kmax[row]  = m;
        g_krinv[row] = 1.f / sred[0];
    }
}

__global__ void k_zero_ctx() {
    g_ctx[blockIdx.x * 1024 + threadIdx.x] = 0.f;
}

// =====================================================================
// Kernel 3: context[b,h,d,e] = sum_n softmax_k(d,n) * v(e,n)
// Split-K over n: grid (16 chunks, NHEAD, BATCH), atomicAdd partials.
// 256 threads = 4 n-subgroups x 64; each thread owns a 4x4 (d,e) tile.
// =====================================================================
__global__ __launch_bounds__(256) void k_context() {
    const int chunk = blockIdx.x;          // 0..15, 2048 tokens each
    const int h = blockIdx.y, b = blockIdx.z;
    const int tid = threadIdx.x;
    const int g = tid >> 6, t = tid & 63;
    const int d0 = (t >> 3) << 2;          // 0,4,..,28
    const int e0 = (t & 7) << 2;           // 0,4,..,28

    __shared__ float sk[32][65];
    __shared__ float sv[32][65];

    const int lr1 = tid >> 4;              // 0..15 (load row)
    const int c4  = (tid & 15) << 2;       // 0..60 (load col)
    const int krow = (b * NHEAD + h) * DHEAD;
    const float km1 = g_kmax[krow + lr1],      ri1 = g_krinv[krow + lr1];
    const float km2 = g_kmax[krow + lr1 + 16], ri2 = g_krinv[krow + lr1 + 16];

    const float* kp = g_qkv + ((size_t)(b * OC3 + HID      + h * DHEAD)) * NTOK;
    const float* vp = g_qkv + ((size_t)(b * OC3 + 2 * HID  + h * DHEAD)) * NTOK;

    float acc[4][4];
#pragma unroll
    for (int i = 0; i < 4; i++)
#pragma unroll
        for (int j = 0; j < 4; j++) acc[i][j] = 0.f;

    const int nchunk0 = chunk * 2048;
    for (int it = 0; it < 32; it++) {
        const int nb = nchunk0 + it * 64;
        float4 kv1 = *(const float4*)&kp[(size_t)lr1 * NTOK + nb + c4];
        float4 kv2 = *(const float4*)&kp[(size_t)(lr1 + 16) * NTOK + nb + c4];
        float4 vv1 = *(const float4*)&vp[(size_t)lr1 * NTOK + nb + c4];
        float4 vv2 = *(const float4*)&vp[(size_t)(lr1 + 16) * NTOK + nb + c4];
        sk[lr1][c4 + 0] = __expf(kv1.x - km1) * ri1;
        sk[lr1][c4 + 1] = __expf(kv1.y - km1) * ri1;
        sk[lr1][c4 + 2] = __expf(kv1.z - km1) * ri1;
        sk[lr1][c4 + 3] = __expf(kv1.w - km1) * ri1;
        sk[lr1 + 16][c4 + 0] = __expf(kv2.x - km2) * ri2;
        sk[lr1 + 16][c4 + 1] = __expf(kv2.y - km2) * ri2;
        sk[lr1 + 16][c4 + 2] = __expf(kv2.z - km2) * ri2;
        sk[lr1 + 16][c4 + 3] = __expf(kv2.w - km2) * ri2;
        sv[lr1][c4 + 0] = vv1.x; sv[lr1][c4 + 1] = vv1.y;
        sv[lr1][c4 + 2] = vv1.z; sv[lr1][c4 + 3] = vv1.w;
        sv[lr1 + 16][c4 + 0] = vv2.x; sv[lr1 + 16][c4 + 1] = vv2.y;
        sv[lr1 + 16][c4 + 2] = vv2.z; sv[lr1 + 16][c4 + 3] = vv2.w;
        __syncthreads();

        const int nnb = g << 4;
#pragma unroll
        for (int s = 0; s < 16; s++) {
            const int nn = nnb + s;
            float ka[4], vb[4];
#pragma unroll
            for (int i = 0; i < 4; i++) ka[i] = sk[d0 + i][nn];
#pragma unroll
            for (int j = 0; j < 4; j++) vb[j] = sv[e0 + j][nn];
#pragma unroll
            for (int i = 0; i < 4; i++)
#pragma unroll
                for (int j = 0; j < 4; j++) acc[i][j] += ka[i] * vb[j];
        }
        __syncthreads();
    }

    float* cp = g_ctx + (size_t)(b * NHEAD + h) * DHEAD * DHEAD;
#pragma unroll
    for (int i = 0; i < 4; i++)
#pragma unroll
        for (int j = 0; j < 4; j++)
            atomicAdd(&cp[(d0 + i) * DHEAD + e0 + j], acc[i][j]);
}

// =====================================================================
// Kernel 4: att[b, h*32+e, n] = sum_d ctx[b,h,d,e] * softmax_d(q)[d,n]*SCALE
// Block = 32 tokens; q-softmax over d fused.
// =====================================================================
__global__ __launch_bounds__(256) void k_attout() {
    const int b  = blockIdx.y;
    const int nb = blockIdx.x * 32;
    const int tid = threadIdx.x;

    __shared__ float sctx[NHEAD * DHEAD * DHEAD];  // 4096
    __shared__ float sq[128][33];

    for (int i = tid; i < 4096; i += 256) sctx[i] = g_ctx[b * 4096 + i];
#pragma unroll
    for (int i = 0; i < 4; i++) {
        int id = tid + i * 256;                    // 1024 float4s
        int row = id >> 3, cc = (id & 7) << 2;
        float4 v = *(const float4*)&g_qkv[((size_t)b * OC3 + row) * NTOK + nb + cc];
        sq[row][cc + 0] = v.x; sq[row][cc + 1] = v.y;
        sq[row][cc + 2] = v.z; sq[row][cc + 3] = v.w;
    }
    __syncthreads();

    if (tid < 128) {                               // softmax over d per (h, n)
        const int h = tid >> 5, n = tid & 31;
        float qv[32];
        float m = -1e30f;
#pragma unroll
        for (int d = 0; d < 32; d++) { qv[d] = sq[h * 32 + d][n]; m = fmaxf(m, qv[d]); }
        float s = 0.f;
#pragma unroll
        for (int d = 0; d < 32; d++) { qv[d] = __expf(qv[d] - m); s += qv[d]; }
        const float r = SCALE / s;
#pragma unroll
        for (int d = 0; d < 32; d++) sq[h * 32 + d][n] = qv[d] * r;
    }
    __syncthreads();

    const int nloc = tid & 31, eh = (tid >> 5) & 1, h = tid >> 6;
    float qv2[32];
#pragma unroll
    for (int d = 0; d < 32; d++) qv2[d] = sq[h * 32 + d][nloc];

    float accf[16];
#pragma unroll
    for (int j = 0; j < 16; j++) accf[j] = 0.f;

    const float* cb = sctx + h * 1024 + eh * 16;
#pragma unroll
    for (int d = 0; d < 32; d++) {
        const float qd = qv2[d];
        const float4* crow = (const float4*)(cb + d * 32);
#pragma unroll
        for (int q4 = 0; q4 < 4; q4++) {
            float4 c = crow[q4];
            accf[q4 * 4 + 0] += c.x * qd;
            accf[q4 * 4 + 1] += c.y * qd;
            accf[q4 * 4 + 2] += c.z * qd;
            accf[q4 * 4 + 3] += c.w * qd;
        }
    }
    float* op = g_att + ((size_t)b * HID + h * DHEAD + eh * 16) * NTOK + nb + nloc;
#pragma unroll
    for (int j = 0; j < 16; j++) op[(size_t)j * NTOK] = accf[j];
}

// =====================================================================
// Kernel 5: y = w_out @ att + bias, then LayerNorm over channels (256),
// gamma/beta. Block = 32 tokens, full M=256.
// =====================================================================
__global__ __launch_bounds__(256) void k_final(const float* __restrict__ wout,
                                               const float* __restrict__ bias,
                                               const float* __restrict__ gamma,
                                               const float* __restrict__ beta,
                                               float* __restrict__ out) {
    const int b  = blockIdx.y;
    const int nb = blockIdx.x * 32;
    const int tid = threadIdx.x;

    __shared__ float satt[128][36];
    __shared__ float As[16][260];
    __shared__ float red[32][33];
    __shared__ float smean[32], srstd[32];

#pragma unroll
    for (int i = 0; i < 4; i++) {
        int id = tid + i * 256;
        int row = id >> 3, cc = (id & 7) << 2;
        float4 v = *(const float4*)&g_att[((size_t)b * HID + row) * NTOK + nb + cc];
        *(float4*)&satt[row][cc] = v;
    }

    const int og = tid >> 3, ng = tid & 7;
    const int o0 = og << 3, n0 = ng << 2;
    float acc[8][4];
#pragma unroll
    for (int i = 0; i < 8; i++)
#pragma unroll
        for (int j = 0; j < 4; j++) acc[i][j] = 0.f;

    for (int kt = 0; kt < 8; kt++) {
#pragma unroll
        for (int i = 0; i < 4; i++) {
            int id = tid + i * 256;
            int o = id >> 2, cc = (id & 3) << 2;
            float4 v = *(const float4*)&wout[(size_t)o * HID + kt * 16 + cc];
            As[cc + 0][o] = v.x; As[cc + 1][o] = v.y;
            As[cc + 2][o] = v.z; As[cc + 3][o] = v.w;
        }
        __syncthreads();
#pragma unroll
        for (int kk = 0; kk < 16; kk++) {
            float4 a0 = *(float4*)&As[kk][o0];
            float4 a1 = *(float4*)&As[kk][o0 + 4];
            float4 b4 = *(float4*)&satt[kt * 16 + kk][n0];
            float av[8] = {a0.x, a0.y, a0.z, a0.w, a1.x, a1.y, a1.z, a1.w};
            float bb[4] = {b4.x, b4.y, b4.z, b4.w};
#pragma unroll
            for (int i = 0; i < 8; i++)
#pragma unroll
                for (int j = 0; j < 4; j++) acc[i][j] += av[i] * bb[j];
        }
        __syncthreads();
    }

    // add bias
#pragma unroll
    for (int i = 0; i < 8; i++) {
        const float bv = bias[o0 + i];
#pragma unroll
        for (int j = 0; j < 4; j++) acc[i][j] += bv;
    }

    // mean over 256 channels (two-pass for stability)
#pragma unroll
    for (int j = 0; j < 4; j++) {
        float s = 0.f;
#pragma unroll
        for (int i = 0; i < 8; i++) s += acc[i][j];
        red[og][n0 + j] = s;
    }
    __syncthreads();
    if (tid < 32) {
        float s = 0.f;
#pragma unroll
        for (int g2 = 0; g2 < 32; g2++) s += red[g2][tid];
        smean[tid] = s * (1.f / 256.f);
    }
    __syncthreads();
#pragma unroll
    for (int j = 0; j < 4; j++) {
        const float mn = smean[n0 + j];
        float s = 0.f;
#pragma unroll
        for (int i = 0; i < 8; i++) { float d = acc[i][j] - mn; s += d * d; }
        red[og][n0 + j] = s;
    }
    __syncthreads();
    if (tid < 32) {
        float s = 0.f;
#pragma unroll
        for (int g2 = 0; g2 < 32; g2++) s += red[g2][tid];
        srstd[tid] = rsqrtf(s * (1.f / 256.f) + LN_EPS);
    }
    __syncthreads();

#pragma unroll
    for (int i = 0; i < 8; i++) {
        const int o = o0 + i;
        const float gm = gamma[o], bt = beta[o];
        float4 v;
        v.x = (acc[i][0] - smean[n0 + 0]) * srstd[n0 + 0] * gm + bt;
        v.y = (acc[i][1] - smean[n0 + 1]) * srstd[n0 + 1] * gm + bt;
        v.z = (acc[i][2] - smean[n0 + 2]) * srstd[n0 + 2] * gm + bt;
        v.w = (acc[i][3] - smean[n0 + 3]) * srstd[n0 + 3] * gm + bt;
        *(float4*)&out[((size_t)b * CIN + o) * NTOK + nb + n0] = v;
    }
}

// =====================================================================
extern "C" void kernel_launch(void* const* d_in, const int* in_sizes, int n_in,
                              void* d_out, int out_size) {
    const float* x      = (const float*)d_in[0];
    const float* w_qkv  = (const float*)d_in[1];
    const float* w_out  = (const float*)d_in[2];
    const float* bias   = (const float*)d_in[3];
    const float* gamma  = (const float*)d_in[4];
    const float* beta   = (const float*)d_in[5];
    float* out = (float*)d_out;

    k_qkv_gemm<<<dim3(NTOK / 64, OC3 / 64, BATCH), 256>>>(x, w_qkv);
    k_zero_ctx<<<16, 1024>>>();
    k_kstats<<<512, 256>>>();
    k_context<<<dim3(16, NHEAD, BATCH), 256>>>();
    k_attout<<<dim3(NTOK / 32, BATCH), 256>>>();
    k_final<<<dim3(NTOK / 32, BATCH), 256>>>(w_out, bias, gamma, beta, out);
}

// round 4
// speedup vs baseline: 1.6058x; 1.6058x over previous
#include <cuda_runtime.h>
#include <cuda_bf16.h>
#include <math.h>
#include <stdint.h>

#define NTOK   32768
#define BATCH  4
#define CIN    256
#define OC3    384
#define HID    128
#define NHEAD  4
#define DHEAD  32
#define SCALE  0.17677669529663687f   // 32^-0.5
#define LN_EPS 1e-5f

// ---------------- scratch (static device globals; no allocation) ----------------
__device__ __align__(16) float g_qkv[(size_t)BATCH * OC3 * NTOK];   // 201 MB
__device__ __align__(16) float g_att[(size_t)BATCH * HID * NTOK];   // 67 MB
__device__ __align__(16) float g_kmax[BATCH * NHEAD * DHEAD];
__device__ __align__(16) float g_krinv[BATCH * NHEAD * DHEAD];
__device__ __align__(16) float g_ctx[BATCH * NHEAD * DHEAD * DHEAD];
// W split planes: [plane(hi=0,lo=1)][mt(3)][chunk(4)][m(128)][k(64)] bf16
__device__ __align__(16) __nv_bfloat16 g_w[2 * 3 * 4 * 128 * 64];   // 768 KB

// ========================= helpers =========================
__device__ __forceinline__ uint32_t smem_u32(const void* p) {
    uint32_t a;
    asm("{ .reg .u64 t; cvta.to.shared.u64 t, %1; cvt.u32.u64 %0, t; }"
        : "=r"(a) : "l"(p));
    return a;
}

#define CP_ASYNC16(dst, src) \
    asm volatile("cp.async.cg.shared.global [%0], [%1], 16;" :: "r"(dst), "l"(src) : "memory")
#define CP_COMMIT() asm volatile("cp.async.commit_group;" ::: "memory")
#define CP_WAIT0()  asm volatile("cp.async.wait_group 0;" ::: "memory")

#define LDSM_X4(r0, r1, r2, r3, addr) \
    asm volatile("ldmatrix.sync.aligned.m8n8.x4.shared.b16 {%0,%1,%2,%3}, [%4];" \
                 : "=r"(r0), "=r"(r1), "=r"(r2), "=r"(r3) : "r"(addr))
#define LDSM_X4_T(r0, r1, r2, r3, addr) \
    asm volatile("ldmatrix.sync.aligned.m8n8.x4.trans.shared.b16 {%0,%1,%2,%3}, [%4];" \
                 : "=r"(r0), "=r"(r1), "=r"(r2), "=r"(r3) : "r"(addr))

#define MMA_16816(c, a, b0, b1) \
    asm volatile("mma.sync.aligned.m16n8k16.row.col.f32.bf16.bf16.f32 " \
                 "{%0,%1,%2,%3}, {%4,%5,%6,%7}, {%8,%9}, {%0,%1,%2,%3};" \
                 : "+f"((c)[0]), "+f"((c)[1]), "+f"((c)[2]), "+f"((c)[3]) \
                 : "r"((a)[0]), "r"((a)[1]), "r"((a)[2]), "r"((a)[3]), "r"(b0), "r"(b1))

// ========================= W pre-split (tiny) =========================
__global__ __launch_bounds__(512) void k_wconv(const float* __restrict__ w) {
    int idx = blockIdx.x * 512 + threadIdx.x;     // o*256 + c
    if (idx >= OC3 * CIN) return;
    int o = idx >> 8, c = idx & 255;
    float v = w[idx];
    __nv_bfloat16 hi = __float2bfloat16(v);
    __nv_bfloat16 lo = __float2bfloat16(v - __bfloat162float(hi));
    int mt = o >> 7, m = o & 127, ch = c >> 6, k = c & 63;
    size_t base = ((size_t)((mt * 4 + ch)) * 128 + m) * 64 + k;
    g_w[base]                            = hi;   // plane 0
    g_w[(size_t)3 * 4 * 128 * 64 + base] = lo;   // plane 1
}

// ========================= QKV GEMM on mma.sync (HMMA) =========================
// qkv[b, mt*128+m, n] = sum_c W[o,c] X[b,c,n], 3-term bf16 split.
// SMEM: A[buf2][plane2][128m][64k] bf16 @0 (64KB), B[buf2][plane2][64k][128n] @65536 (64KB)
#define QKV_SMEM 131072
#define QB_OFF   65536

__global__ __launch_bounds__(256, 1) void k_qkv_mma(const float* __restrict__ x) {
    extern __shared__ __align__(1024) char smem[];
    const uint32_t sb = smem_u32(smem);
    const int b = blockIdx.z, mt = blockIdx.y;
    const int n0 = blockIdx.x * 128;
    const int tid = threadIdx.x, wid = tid >> 5, lane = tid & 31;
    const int warp_m = wid >> 2, warp_n = wid & 3;
    const float* xb = x + (size_t)b * CIN * NTOK + n0;

    float acc[4][4][4];
#pragma unroll
    for (int i = 0; i < 4; i++)
#pragma unroll
        for (int j = 0; j < 4; j++)
#pragma unroll
            for (int r = 0; r < 4; r++) acc[i][j][r] = 0.f;

    // ---- W cp.async (both planes) for chunk c into buffer buf ----
    // W tile: 128 m-rows x 128 bytes (64 bf16) = 1024 16-byte units, 8 units/row.
#define WCP(c, buf) do { \
    _Pragma("unroll") \
    for (int p = 0; p < 2; p++) { \
        const char* srcb = (const char*)g_w + (((size_t)(p * 3 + mt) * 4 + (c))) * 16384; \
        _Pragma("unroll") \
        for (int i = 0; i < 4; i++) { \
            int u = tid + 256 * i;               /* 0..1023 16B units */ \
            int m = u >> 3, ks = u & 7; \
            uint32_t dst = sb + (buf) * 32768 + p * 16384 + m * 128 + ((ks * 16) ^ ((m & 7) << 4)); \
            CP_ASYNC16(dst, srcb + (size_t)u * 16); \
        } \
    } \
} while (0)

    // ---- X LDG chunk c into regs ----
    float4 xr[8];
#define XLDG(c) do { \
    _Pragma("unroll") \
    for (int i = 0; i < 8; i++) { \
        int r = wid + 8 * i; \
        xr[i] = *(const float4*)&xb[(size_t)((c) * 64 + r) * NTOK + lane * 4]; \
    } \
} while (0)

    // ---- convert + STS X regs into buffer buf ----
#define XSTS(buf) do { \
    _Pragma("unroll") \
    for (int i = 0; i < 8; i++) { \
        int r = wid + 8 * i; \
        float4 v = xr[i]; \
        __nv_bfloat16 h0 = __float2bfloat16(v.x), h1 = __float2bfloat16(v.y); \
        __nv_bfloat16 h2 = __float2bfloat16(v.z), h3 = __float2bfloat16(v.w); \
        __nv_bfloat16 l0 = __float2bfloat16(v.x - __bfloat162float(h0)); \
        __nv_bfloat16 l1 = __float2bfloat16(v.y - __bfloat162float(h1)); \
        __nv_bfloat16 l2 = __float2bfloat16(v.z - __bfloat162float(h2)); \
        __nv_bfloat16 l3 = __float2bfloat16(v.w - __bfloat162float(h3)); \
        uint2 hv = make_uint2((uint32_t)__bfloat16_as_ushort(h0) | ((uint32_t)__bfloat16_as_ushort(h1) << 16), \
                              (uint32_t)__bfloat16_as_ushort(h2) | ((uint32_t)__bfloat16_as_ushort(h3) << 16)); \
        uint2 lv = make_uint2((uint32_t)__bfloat16_as_ushort(l0) | ((uint32_t)__bfloat16_as_ushort(l1) << 16), \
                              (uint32_t)__bfloat16_as_ushort(l2) | ((uint32_t)__bfloat16_as_ushort(l3) << 16)); \
        uint32_t off = (uint32_t)r * 256 + (((uint32_t)lane * 8) ^ (((uint32_t)r & 7) << 4)); \
        *(uint2*)(smem + QB_OFF + (buf) * 32768 + off)         = hv; \
        *(uint2*)(smem + QB_OFF + (buf) * 32768 + 16384 + off) = lv; \
    } \
} while (0)

    // prologue: chunk 0
    XLDG(0);
    WCP(0, 0);
    CP_COMMIT();
    XSTS(0);
    CP_WAIT0();
    __syncthreads();

    const int lm = lane & 15;             // row-within-16 for ldmatrix
    const int khalf = (lane >> 4) << 3;   // +8 for upper half

    for (int c = 0; c < 4; ++c) {
        const int cur = c & 1, nxt = cur ^ 1;
        if (c < 3) {
            WCP(c + 1, nxt);
            CP_COMMIT();
            XLDG(c + 1);
        }

        // ---- mma phase: 3 terms x 4 k-steps on buffer cur ----
#pragma unroll
        for (int t3 = 0; t3 < 3; t3++) {
            const int pa = (t3 == 2) ? 1 : 0;     // A plane: hi,hi,lo
            const int pb = (t3 == 1) ? 1 : 0;     // B plane: hi,lo,hi
            const uint32_t abase = sb + cur * 32768 + pa * 16384;
            const uint32_t bbase = sb + QB_OFF + cur * 32768 + pb * 16384;
#pragma unroll
            for (int ks = 0; ks < 4; ks++) {
                uint32_t ar[4][4];
#pragma unroll
                for (int im = 0; im < 4; im++) {
                    uint32_t m_row = (uint32_t)(warp_m * 64 + im * 16 + lm);
                    uint32_t k_off = (uint32_t)(ks * 16 + khalf);
                    uint32_t addr = abase + m_row * 128 + ((k_off * 2) ^ ((m_row & 7) << 4));
                    LDSM_X4(ar[im][0], ar[im][1], ar[im][2], ar[im][3], addr);
                }
                uint32_t br[2][4];
#pragma unroll
                for (int jn = 0; jn < 2; jn++) {
                    uint32_t k_row = (uint32_t)(ks * 16 + lm);
                    uint32_t n_off = (uint32_t)(warp_n * 32 + jn * 16 + khalf);
                    uint32_t addr = bbase + k_row * 256 + ((n_off * 2) ^ ((k_row & 7) << 4));
                    LDSM_X4_T(br[jn][0], br[jn][1], br[jn][2], br[jn][3], addr);
                }
#pragma unroll
                for (int im = 0; im < 4; im++) {
#pragma unroll
                    for (int jn = 0; jn < 2; jn++) {
                        MMA_16816(acc[im][jn * 2 + 0], ar[im], br[jn][0], br[jn][1]);
                        MMA_16816(acc[im][jn * 2 + 1], ar[im], br[jn][2], br[jn][3]);
                    }
                }
            }
        }

        if (c < 3) {
            XSTS(nxt);
            CP_WAIT0();
        }
        __syncthreads();
    }

    // ---- epilogue: direct STG ----
    const int g = lane >> 2, tig = lane & 3;
    float* outb = g_qkv + ((size_t)b * OC3 + mt * 128) * NTOK + n0;
#pragma unroll
    for (int im = 0; im < 4; im++) {
        const int row = warp_m * 64 + im * 16 + g;
#pragma unroll
        for (int jn = 0; jn < 4; jn++) {
            const int col = warp_n * 32 + jn * 8 + tig * 2;
            *(float2*)&outb[(size_t)row * NTOK + col] =
                make_float2(acc[im][jn][0], acc[im][jn][1]);
            *(float2*)&outb[(size_t)(row + 8) * NTOK + col] =
                make_float2(acc[im][jn][2], acc[im][jn][3]);
        }
    }
#undef WCP
#undef XLDG
#undef XSTS
}

// =====================================================================
// Kernel 2: per-row (b,h,d) max and 1/sum(exp) for k-softmax over n.
// =====================================================================
__global__ __launch_bounds__(256) void k_kstats() {
    const int row = blockIdx.x;
    const int b = row >> 7, lr = row & 127;
    const float* p = g_qkv + ((size_t)b * OC3 + HID + lr) * NTOK;
    __shared__ float sred[256];
    const int tid = threadIdx.x;

    float m = -1e30f;
    for (int i = tid * 4; i < NTOK; i += 1024) {
        float4 v = *(const float4*)&p[i];
        m = fmaxf(m, fmaxf(fmaxf(v.x, v.y), fmaxf(v.z, v.w)));
    }
    sred[tid] = m;
    __syncthreads();
    for (int s = 128; s > 0; s >>= 1) {
        if (tid < s) sred[tid] = fmaxf(sred[tid], sred[tid + s]);
        __syncthreads();
    }
    m = sred[0];
    __syncthreads();

    float sum = 0.f;
    for (int i = tid * 4; i < NTOK; i += 1024) {
        float4 v = *(const float4*)&p[i];
        sum += __expf(v.x - m) + __expf(v.y - m) + __expf(v.z - m) + __expf(v.w - m);
    }
    sred[tid] = sum;
    __syncthreads();
    for (int s = 128; s > 0; s >>= 1) {
        if (tid < s) sred[tid] += sred[tid + s];
        __syncthreads();
    }
    if (tid == 0) {
        g_kmax[row]  = m;
        g_krinv[row] = 1.f / sred[0];
    }
}

__global__ void k_zero_ctx() {
    g_ctx[blockIdx.x * 1024 + threadIdx.x] = 0.f;
}

// =====================================================================
// Kernel 3: context[b,h,d,e] = sum_n softmax_k(d,n) * v(e,n)
// =====================================================================
__global__ __launch_bounds__(256) void k_context() {
    const int chunk = blockIdx.x;
    const int h = blockIdx.y, b = blockIdx.z;
    const int tid = threadIdx.x;
    const int g = tid >> 6, t = tid & 63;
    const int d0 = (t >> 3) << 2;
    const int e0 = (t & 7) << 2;

    __shared__ float sk[32][65];
    __shared__ float sv[32][65];

    const int lr1 = tid >> 4;
    const int c4  = (tid & 15) << 2;
    const int krow = (b * NHEAD + h) * DHEAD;
    const float km1 = g_kmax[krow + lr1],      ri1 = g_krinv[krow + lr1];
    const float km2 = g_kmax[krow + lr1 + 16], ri2 = g_krinv[krow + lr1 + 16];

    const float* kp = g_qkv + ((size_t)(b * OC3 + HID      + h * DHEAD)) * NTOK;
    const float* vp = g_qkv + ((size_t)(b * OC3 + 2 * HID  + h * DHEAD)) * NTOK;

    float acc[4][4];
#pragma unroll
    for (int i = 0; i < 4; i++)
#pragma unroll
        for (int j = 0; j < 4; j++) acc[i][j] = 0.f;

    const int nchunk0 = chunk * 2048;
    for (int it = 0; it < 32; it++) {
        const int nb = nchunk0 + it * 64;
        float4 kv1 = *(const float4*)&kp[(size_t)lr1 * NTOK + nb + c4];
        float4 kv2 = *(const float4*)&kp[(size_t)(lr1 + 16) * NTOK + nb + c4];
        float4 vv1 = *(const float4*)&vp[(size_t)lr1 * NTOK + nb + c4];
        float4 vv2 = *(const float4*)&vp[(size_t)(lr1 + 16) * NTOK + nb + c4];
        sk[lr1][c4 + 0] = __expf(kv1.x - km1) * ri1;
        sk[lr1][c4 + 1] = __expf(kv1.y - km1) * ri1;
        sk[lr1][c4 + 2] = __expf(kv1.z - km1) * ri1;
        sk[lr1][c4 + 3] = __expf(kv1.w - km1) * ri1;
        sk[lr1 + 16][c4 + 0] = __expf(kv2.x - km2) * ri2;
        sk[lr1 + 16][c4 + 1] = __expf(kv2.y - km2) * ri2;
        sk[lr1 + 16][c4 + 2] = __expf(kv2.z - km2) * ri2;
        sk[lr1 + 16][c4 + 3] = __expf(kv2.w - km2) * ri2;
        sv[lr1][c4 + 0] = vv1.x; sv[lr1][c4 + 1] = vv1.y;
        sv[lr1][c4 + 2] = vv1.z; sv[lr1][c4 + 3] = vv1.w;
        sv[lr1 + 16][c4 + 0] = vv2.x; sv[lr1 + 16][c4 + 1] = vv2.y;
        sv[lr1 + 16][c4 + 2] = vv2.z; sv[lr1 + 16][c4 + 3] = vv2.w;
        __syncthreads();

        const int nnb = g << 4;
#pragma unroll
        for (int s = 0; s < 16; s++) {
            const int nn = nnb + s;
            float ka[4], vb[4];
#pragma unroll
            for (int i = 0; i < 4; i++) ka[i] = sk[d0 + i][nn];
#pragma unroll
            for (int j = 0; j < 4; j++) vb[j] = sv[e0 + j][nn];
#pragma unroll
            for (int i = 0; i < 4; i++)
#pragma unroll
                for (int j = 0; j < 4; j++) acc[i][j] += ka[i] * vb[j];
        }
        __syncthreads();
    }

    float* cp = g_ctx + (size_t)(b * NHEAD + h) * DHEAD * DHEAD;
#pragma unroll
    for (int i = 0; i < 4; i++)
#pragma unroll
        for (int j = 0; j < 4; j++)
            atomicAdd(&cp[(d0 + i) * DHEAD + e0 + j], acc[i][j]);
}

// =====================================================================
// Kernel 4: att[b, h*32+e, n] = sum_d ctx[b,h,d,e] * softmax_d(q)[d,n]*SCALE
// =====================================================================
__global__ __launch_bounds__(256) void k_attout() {
    const int b  = blockIdx.y;
    const int nb = blockIdx.x * 32;
    const int tid = threadIdx.x;

    __shared__ float sctx[NHEAD * DHEAD * DHEAD];
    __shared__ float sq[128][33];

    for (int i = tid; i < 4096; i += 256) sctx[i] = g_ctx[b * 4096 + i];
#pragma unroll
    for (int i = 0; i < 4; i++) {
        int id = tid + i * 256;
        int row = id >> 3, cc = (id & 7) << 2;
        float4 v = *(const float4*)&g_qkv[((size_t)b * OC3 + row) * NTOK + nb + cc];
        sq[row][cc + 0] = v.x; sq[row][cc + 1] = v.y;
        sq[row][cc + 2] = v.z; sq[row][cc + 3] = v.w;
    }
    __syncthreads();

    if (tid < 128) {
        const int h = tid >> 5, n = tid & 31;
        float qv[32];
        float m = -1e30f;
#pragma unroll
        for (int d = 0; d < 32; d++) { qv[d] = sq[h * 32 + d][n]; m = fmaxf(m, qv[d]); }
        float s = 0.f;
#pragma unroll
        for (int d = 0; d < 32; d++) { qv[d] = __expf(qv[d] - m); s += qv[d]; }
        const float r = SCALE / s;
#pragma unroll
        for (int d = 0; d < 32; d++) sq[h * 32 + d][n] = qv[d] * r;
    }
    __syncthreads();

    const int nloc = tid & 31, eh = (tid >> 5) & 1, h = tid >> 6;
    float qv2[32];
#pragma unroll
    for (int d = 0; d < 32; d++) qv2[d] = sq[h * 32 + d][nloc];

    float accf[16];
#pragma unroll
    for (int j = 0; j < 16; j++) accf[j] = 0.f;

    const float* cb = sctx + h * 1024 + eh * 16;
#pragma unroll
    for (int d = 0; d < 32; d++) {
        const float qd = qv2[d];
        const float4* crow = (const float4*)(cb + d * 32);
#pragma unroll
        for (int q4 = 0; q4 < 4; q4++) {
            float4 c = crow[q4];
            accf[q4 * 4 + 0] += c.x * qd;
            accf[q4 * 4 + 1] += c.y * qd;
            accf[q4 * 4 + 2] += c.z * qd;
            accf[q4 * 4 + 3] += c.w * qd;
        }
    }
    float* op = g_att + ((size_t)b * HID + h * DHEAD + eh * 16) * NTOK + nb + nloc;
#pragma unroll
    for (int j = 0; j < 16; j++) op[(size_t)j * NTOK] = accf[j];
}

// =====================================================================
// Kernel 5: y = w_out @ att + bias, then LayerNorm over 256 channels.
// =====================================================================
__global__ __launch_bounds__(256) void k_final(const float* __restrict__ wout,
                                               const float* __restrict__ bias,
                                               const float* __restrict__ gamma,
                                               const float* __restrict__ beta,
                                               float* __restrict__ out) {
    const int b  = blockIdx.y;
    const int nb = blockIdx.x * 32;
    const int tid = threadIdx.x;

    __shared__ float satt[128][36];
    __shared__ float As[16][260];
    __shared__ float red[32][33];
    __shared__ float smean[32], srstd[32];

#pragma unroll
    for (int i = 0; i < 4; i++) {
        int id = tid + i * 256;
        int row = id >> 3, cc = (id & 7) << 2;
        float4 v = *(const float4*)&g_att[((size_t)b * HID + row) * NTOK + nb + cc];
        *(float4*)&satt[row][cc] = v;
    }

    const int og = tid >> 3, ng = tid & 7;
    const int o0 = og << 3, n0 = ng << 2;
    float acc[8][4];
#pragma unroll
    for (int i = 0; i < 8; i++)
#pragma unroll
        for (int j = 0; j < 4; j++) acc[i][j] = 0.f;

    for (int kt = 0; kt < 8; kt++) {
#pragma unroll
        for (int i = 0; i < 4; i++) {
            int id = tid + i * 256;
            int o = id >> 2, cc = (id & 3) << 2;
            float4 v = *(const float4*)&wout[(size_t)o * HID + kt * 16 + cc];
            As[cc + 0][o] = v.x; As[cc + 1][o] = v.y;
            As[cc + 2][o] = v.z; As[cc + 3][o] = v.w;
        }
        __syncthreads();
#pragma unroll
        for (int kk = 0; kk < 16; kk++) {
            float4 a0 = *(float4*)&As[kk][o0];
            float4 a1 = *(float4*)&As[kk][o0 + 4];
            float4 b4 = *(float4*)&satt[kt * 16 + kk][n0];
            float av[8] = {a0.x, a0.y, a0.z, a0.w, a1.x, a1.y, a1.z, a1.w};
            float bb[4] = {b4.x, b4.y, b4.z, b4.w};
#pragma unroll
            for (int i = 0; i < 8; i++)
#pragma unroll
                for (int j = 0; j < 4; j++) acc[i][j] += av[i] * bb[j];
        }
        __syncthreads();
    }

#pragma unroll
    for (int i = 0; i < 8; i++) {
        const float bv = bias[o0 + i];
#pragma unroll
        for (int j = 0; j < 4; j++) acc[i][j] += bv;
    }

#pragma unroll
    for (int j = 0; j < 4; j++) {
        float s = 0.f;
#pragma unroll
        for (int i = 0; i < 8; i++) s += acc[i][j];
        red[og][n0 + j] = s;
    }
    __syncthreads();
    if (tid < 32) {
        float s = 0.f;
#pragma unroll
        for (int g2 = 0; g2 < 32; g2++) s += red[g2][tid];
        smean[tid] = s * (1.f / 256.f);
    }
    __syncthreads();
#pragma unroll
    for (int j = 0; j < 4; j++) {
        const float mn = smean[n0 + j];
        float s = 0.f;
#pragma unroll
        for (int i = 0; i < 8; i++) { float d = acc[i][j] - mn; s += d * d; }
        red[og][n0 + j] = s;
    }
    __syncthreads();
    if (tid < 32) {
        float s = 0.f;
#pragma unroll
        for (int g2 = 0; g2 < 32; g2++) s += red[g2][tid];
        srstd[tid] = rsqrtf(s * (1.f / 256.f) + LN_EPS);
    }
    __syncthreads();

#pragma unroll
    for (int i = 0; i < 8; i++) {
        const int o = o0 + i;
        const float gm = gamma[o], bt = beta[o];
        float4 v;
        v.x = (acc[i][0] - smean[n0 + 0]) * srstd[n0 + 0] * gm + bt;
        v.y = (acc[i][1] - smean[n0 + 1]) * srstd[n0 + 1] * gm + bt;
        v.z = (acc[i][2] - smean[n0 + 2]) * srstd[n0 + 2] * gm + bt;
        v.w = (acc[i][3] - smean[n0 + 3]) * srstd[n0 + 3] * gm + bt;
        *(float4*)&out[((size_t)b * CIN + o) * NTOK + nb + n0] = v;
    }
}

// =====================================================================
extern "C" void kernel_launch(void* const* d_in, const int* in_sizes, int n_in,
                              void* d_out, int out_size) {
    const float* x      = (const float*)d_in[0];
    const float* w_qkv  = (const float*)d_in[1];
    const float* w_out  = (const float*)d_in[2];
    const float* bias   = (const float*)d_in[3];
    const float* gamma  = (const float*)d_in[4];
    const float* beta   = (const float*)d_in[5];
    float* out = (float*)d_out;

    cudaFuncSetAttribute(k_qkv_mma, cudaFuncAttributeMaxDynamicSharedMemorySize,
                         QKV_SMEM);

    k_wconv<<<192, 512>>>(w_qkv);
    k_qkv_mma<<<dim3(NTOK / 128, 3, BATCH), 256, QKV_SMEM>>>(x);
    k_zero_ctx<<<16, 1024>>>();
    k_kstats<<<512, 256>>>();
    k_context<<<dim3(16, NHEAD, BATCH), 256>>>();
    k_attout<<<dim3(NTOK / 32, BATCH), 256>>>();
    k_final<<<dim3(NTOK / 32, BATCH), 256>>>(w_out, bias, gamma, beta, out);
}

// round 5
// speedup vs baseline: 1.7138x; 1.0673x over previous
#include <cuda_runtime.h>
#include <cuda_bf16.h>
#include <math.h>
#include <stdint.h>

#define NTOK   32768
#define BATCH  4
#define CIN    256
#define OC3    384
#define HID    128
#define NHEAD  4
#define DHEAD  32
#define SCALE  0.17677669529663687f   // 32^-0.5
#define LN_EPS 1e-5f

// ---------------- scratch (static device globals; no allocation) ----------------
__device__ __align__(16) float g_qkv[(size_t)BATCH * OC3 * NTOK];   // 201 MB
__device__ __align__(16) float g_kmax[BATCH * NHEAD * DHEAD];
__device__ __align__(16) float g_krinv[BATCH * NHEAD * DHEAD];
__device__ __align__(16) float g_ctx[BATCH * NHEAD * DHEAD * DHEAD];
// W_qkv split planes: [plane(hi,lo)][mt(3)][chunk(4)][m(128)][k(64)] bf16
__device__ __align__(16) __nv_bfloat16 g_w[2 * 3 * 4 * 128 * 64];   // 768 KB
// W_out split planes: [plane(hi,lo)][o(256)][c(128)] bf16
__device__ __align__(16) __nv_bfloat16 g_w2[2 * 256 * 128];         // 128 KB

// ========================= helpers =========================
__device__ __forceinline__ uint32_t smem_u32(const void* p) {
    uint32_t a;
    asm("{ .reg .u64 t; cvta.to.shared.u64 t, %1; cvt.u32.u64 %0, t; }"
        : "=r"(a) : "l"(p));
    return a;
}

#define CP_ASYNC16(dst, src) \
    asm volatile("cp.async.cg.shared.global [%0], [%1], 16;" :: "r"(dst), "l"(src) : "memory")
#define CP_COMMIT() asm volatile("cp.async.commit_group;" ::: "memory")
#define CP_WAIT0()  asm volatile("cp.async.wait_group 0;" ::: "memory")

#define LDSM_X4(r0, r1, r2, r3, addr) \
    asm volatile("ldmatrix.sync.aligned.m8n8.x4.shared.b16 {%0,%1,%2,%3}, [%4];" \
                 : "=r"(r0), "=r"(r1), "=r"(r2), "=r"(r3) : "r"(addr))
#define LDSM_X4_T(r0, r1, r2, r3, addr) \
    asm volatile("ldmatrix.sync.aligned.m8n8.x4.trans.shared.b16 {%0,%1,%2,%3}, [%4];" \
                 : "=r"(r0), "=r"(r1), "=r"(r2), "=r"(r3) : "r"(addr))

#define MMA_16816(c, a, b0, b1) \
    asm volatile("mma.sync.aligned.m16n8k16.row.col.f32.bf16.bf16.f32 " \
                 "{%0,%1,%2,%3}, {%4,%5,%6,%7}, {%8,%9}, {%0,%1,%2,%3};" \
                 : "+f"((c)[0]), "+f"((c)[1]), "+f"((c)[2]), "+f"((c)[3]) \
                 : "r"((a)[0]), "r"((a)[1]), "r"((a)[2]), "r"((a)[3]), "r"(b0), "r"(b1))

__device__ __forceinline__ void bf16_split(float v, __nv_bfloat16& hi, __nv_bfloat16& lo) {
    hi = __float2bfloat16(v);
    lo = __float2bfloat16(v - __bfloat162float(hi));
}

// ========================= W pre-split kernels (tiny) =========================
__global__ __launch_bounds__(512) void k_wconv(const float* __restrict__ w) {
    int idx = blockIdx.x * 512 + threadIdx.x;     // o*256 + c
    if (idx >= OC3 * CIN) return;
    int o = idx >> 8, c = idx & 255;
    __nv_bfloat16 hi, lo;
    bf16_split(w[idx], hi, lo);
    int mt = o >> 7, m = o & 127, ch = c >> 6, k = c & 63;
    size_t base = ((size_t)((mt * 4 + ch)) * 128 + m) * 64 + k;
    g_w[base]                            = hi;
    g_w[(size_t)3 * 4 * 128 * 64 + base] = lo;
}

__global__ __launch_bounds__(512) void k_wconv2(const float* __restrict__ w) {
    int idx = blockIdx.x * 512 + threadIdx.x;     // o*128 + c
    if (idx >= CIN * HID) return;
    __nv_bfloat16 hi, lo;
    bf16_split(w[idx], hi, lo);
    g_w2[idx]              = hi;
    g_w2[CIN * HID + idx]  = lo;
}

// ========================= QKV GEMM on mma.sync (HMMA) =========================
#define QKV_SMEM 131072
#define QB_OFF   65536

__global__ __launch_bounds__(256, 1) void k_qkv_mma(const float* __restrict__ x) {
    extern __shared__ __align__(1024) char smem[];
    const uint32_t sb = smem_u32(smem);
    const int b = blockIdx.z, mt = blockIdx.y;
    const int n0 = blockIdx.x * 128;
    const int tid = threadIdx.x, wid = tid >> 5, lane = tid & 31;
    const int warp_m = wid >> 2, warp_n = wid & 3;
    const float* xb = x + (size_t)b * CIN * NTOK + n0;

    float acc[4][4][4];
#pragma unroll
    for (int i = 0; i < 4; i++)
#pragma unroll
        for (int j = 0; j < 4; j++)
#pragma unroll
            for (int r = 0; r < 4; r++) acc[i][j][r] = 0.f;

#define WCP(c, buf) do { \
    _Pragma("unroll") \
    for (int p = 0; p < 2; p++) { \
        const char* srcb = (const char*)g_w + (((size_t)(p * 3 + mt) * 4 + (c))) * 16384; \
        _Pragma("unroll") \
        for (int i = 0; i < 4; i++) { \
            int u = tid + 256 * i; \
            int m = u >> 3, ks = u & 7; \
            uint32_t dst = sb + (buf) * 32768 + p * 16384 + m * 128 + ((ks * 16) ^ ((m & 7) << 4)); \
            CP_ASYNC16(dst, srcb + (size_t)u * 16); \
        } \
    } \
} while (0)

    float4 xr[8];
#define XLDG(c) do { \
    _Pragma("unroll") \
    for (int i = 0; i < 8; i++) { \
        int r = wid + 8 * i; \
        xr[i] = *(const float4*)&xb[(size_t)((c) * 64 + r) * NTOK + lane * 4]; \
    } \
} while (0)

#define XSTS(buf) do { \
    _Pragma("unroll") \
    for (int i = 0; i < 8; i++) { \
        int r = wid + 8 * i; \
        float4 v = xr[i]; \
        __nv_bfloat16 h0, h1, h2, h3, l0, l1, l2, l3; \
        bf16_split(v.x, h0, l0); bf16_split(v.y, h1, l1); \
        bf16_split(v.z, h2, l2); bf16_split(v.w, h3, l3); \
        uint2 hv = make_uint2((uint32_t)__bfloat16_as_ushort(h0) | ((uint32_t)__bfloat16_as_ushort(h1) << 16), \
                              (uint32_t)__bfloat16_as_ushort(h2) | ((uint32_t)__bfloat16_as_ushort(h3) << 16)); \
        uint2 lv = make_uint2((uint32_t)__bfloat16_as_ushort(l0) | ((uint32_t)__bfloat16_as_ushort(l1) << 16), \
                              (uint32_t)__bfloat16_as_ushort(l2) | ((uint32_t)__bfloat16_as_ushort(l3) << 16)); \
        uint32_t off = (uint32_t)r * 256 + (((uint32_t)lane * 8) ^ (((uint32_t)r & 7) << 4)); \
        *(uint2*)(smem + QB_OFF + (buf) * 32768 + off)         = hv; \
        *(uint2*)(smem + QB_OFF + (buf) * 32768 + 16384 + off) = lv; \
    } \
} while (0)

    XLDG(0);
    WCP(0, 0);
    CP_COMMIT();
    XSTS(0);
    CP_WAIT0();
    __syncthreads();

    const int lm = lane & 15;
    const int khalf = (lane >> 4) << 3;

    for (int c = 0; c < 4; ++c) {
        const int cur = c & 1, nxt = cur ^ 1;
        if (c < 3) {
            WCP(c + 1, nxt);
            CP_COMMIT();
            XLDG(c + 1);
        }

#pragma unroll
        for (int t3 = 0; t3 < 3; t3++) {
            const int pa = (t3 == 2) ? 1 : 0;
            const int pb = (t3 == 1) ? 1 : 0;
            const uint32_t abase = sb + cur * 32768 + pa * 16384;
            const uint32_t bbase = sb + QB_OFF + cur * 32768 + pb * 16384;
#pragma unroll
            for (int ks = 0; ks < 4; ks++) {
                uint32_t ar[4][4];
#pragma unroll
                for (int im = 0; im < 4; im++) {
                    uint32_t m_row = (uint32_t)(warp_m * 64 + im * 16 + lm);
                    uint32_t k_off = (uint32_t)(ks * 16 + khalf);
                    uint32_t addr = abase + m_row * 128 + ((k_off * 2) ^ ((m_row & 7) << 4));
                    LDSM_X4(ar[im][0], ar[im][1], ar[im][2], ar[im][3], addr);
                }
                uint32_t br[2][4];
#pragma unroll
                for (int jn = 0; jn < 2; jn++) {
                    uint32_t k_row = (uint32_t)(ks * 16 + lm);
                    uint32_t n_off = (uint32_t)(warp_n * 32 + jn * 16 + khalf);
                    uint32_t addr = bbase + k_row * 256 + ((n_off * 2) ^ ((k_row & 7) << 4));
                    LDSM_X4_T(br[jn][0], br[jn][1], br[jn][2], br[jn][3], addr);
                }
#pragma unroll
                for (int im = 0; im < 4; im++) {
#pragma unroll
                    for (int jn = 0; jn < 2; jn++) {
                        MMA_16816(acc[im][jn * 2 + 0], ar[im], br[jn][0], br[jn][1]);
                        MMA_16816(acc[im][jn * 2 + 1], ar[im], br[jn][2], br[jn][3]);
                    }
                }
            }
        }

        if (c < 3) {
            XSTS(nxt);
            CP_WAIT0();
        }
        __syncthreads();
    }

    const int g = lane >> 2, tig = lane & 3;
    float* outb = g_qkv + ((size_t)b * OC3 + mt * 128) * NTOK + n0;
#pragma unroll
    for (int im = 0; im < 4; im++) {
        const int row = warp_m * 64 + im * 16 + g;
#pragma unroll
        for (int jn = 0; jn < 4; jn++) {
            const int col = warp_n * 32 + jn * 8 + tig * 2;
            *(float2*)&outb[(size_t)row * NTOK + col] =
                make_float2(acc[im][jn][0], acc[im][jn][1]);
            *(float2*)&outb[(size_t)(row + 8) * NTOK + col] =
                make_float2(acc[im][jn][2], acc[im][jn][3]);
        }
    }
#undef WCP
#undef XLDG
#undef XSTS
}

// =====================================================================
// Kernel 2: per-row (b,h,d) max and 1/sum(exp) for k-softmax over n.
// =====================================================================
__global__ __launch_bounds__(256) void k_kstats() {
    const int row = blockIdx.x;
    const int b = row >> 7, lr = row & 127;
    const float* p = g_qkv + ((size_t)b * OC3 + HID + lr) * NTOK;
    __shared__ float sred[256];
    const int tid = threadIdx.x;

    float m = -1e30f;
    for (int i = tid * 4; i < NTOK; i += 1024) {
        float4 v = *(const float4*)&p[i];
        m = fmaxf(m, fmaxf(fmaxf(v.x, v.y), fmaxf(v.z, v.w)));
    }
    sred[tid] = m;
    __syncthreads();
    for (int s = 128; s > 0; s >>= 1) {
        if (tid < s) sred[tid] = fmaxf(sred[tid], sred[tid + s]);
        __syncthreads();
    }
    m = sred[0];
    __syncthreads();

    float sum = 0.f;
    for (int i = tid * 4; i < NTOK; i += 1024) {
        float4 v = *(const float4*)&p[i];
        sum += __expf(v.x - m) + __expf(v.y - m) + __expf(v.z - m) + __expf(v.w - m);
    }
    sred[tid] = sum;
    __syncthreads();
    for (int s = 128; s > 0; s >>= 1) {
        if (tid < s) sred[tid] += sred[tid + s];
        __syncthreads();
    }
    if (tid == 0) {
        g_kmax[row]  = m;
        g_krinv[row] = 1.f / sred[0];
    }
}

__global__ void k_zero_ctx() {
    g_ctx[blockIdx.x * 1024 + threadIdx.x] = 0.f;
}

// =====================================================================
// Kernel 3: context[b,h,d,e] = sum_n softmax_k(d,n) * v(e,n)
// =====================================================================
__global__ __launch_bounds__(256) void k_context() {
    const int chunk = blockIdx.x;
    const int h = blockIdx.y, b = blockIdx.z;
    const int tid = threadIdx.x;
    const int g = tid >> 6, t = tid & 63;
    const int d0 = (t >> 3) << 2;
    const int e0 = (t & 7) << 2;

    __shared__ float sk[32][65];
    __shared__ float sv[32][65];

    const int lr1 = tid >> 4;
    const int c4  = (tid & 15) << 2;
    const int krow = (b * NHEAD + h) * DHEAD;
    const float km1 = g_kmax[krow + lr1],      ri1 = g_krinv[krow + lr1];
    const float km2 = g_kmax[krow + lr1 + 16], ri2 = g_krinv[krow + lr1 + 16];

    const float* kp = g_qkv + ((size_t)(b * OC3 + HID      + h * DHEAD)) * NTOK;
    const float* vp = g_qkv + ((size_t)(b * OC3 + 2 * HID  + h * DHEAD)) * NTOK;

    float acc[4][4];
#pragma unroll
    for (int i = 0; i < 4; i++)
#pragma unroll
        for (int j = 0; j < 4; j++) acc[i][j] = 0.f;

    const int nchunk0 = chunk * 2048;
    for (int it = 0; it < 32; it++) {
        const int nb = nchunk0 + it * 64;
        float4 kv1 = *(const float4*)&kp[(size_t)lr1 * NTOK + nb + c4];
        float4 kv2 = *(const float4*)&kp[(size_t)(lr1 + 16) * NTOK + nb + c4];
        float4 vv1 = *(const float4*)&vp[(size_t)lr1 * NTOK + nb + c4];
        float4 vv2 = *(const float4*)&vp[(size_t)(lr1 + 16) * NTOK + nb + c4];
        sk[lr1][c4 + 0] = __expf(kv1.x - km1) * ri1;
        sk[lr1][c4 + 1] = __expf(kv1.y - km1) * ri1;
        sk[lr1][c4 + 2] = __expf(kv1.z - km1) * ri1;
        sk[lr1][c4 + 3] = __expf(kv1.w - km1) * ri1;
        sk[lr1 + 16][c4 + 0] = __expf(kv2.x - km2) * ri2;
        sk[lr1 + 16][c4 + 1] = __expf(kv2.y - km2) * ri2;
        sk[lr1 + 16][c4 + 2] = __expf(kv2.z - km2) * ri2;
        sk[lr1 + 16][c4 + 3] = __expf(kv2.w - km2) * ri2;
        sv[lr1][c4 + 0] = vv1.x; sv[lr1][c4 + 1] = vv1.y;
        sv[lr1][c4 + 2] = vv1.z; sv[lr1][c4 + 3] = vv1.w;
        sv[lr1 + 16][c4 + 0] = vv2.x; sv[lr1 + 16][c4 + 1] = vv2.y;
        sv[lr1 + 16][c4 + 2] = vv2.z; sv[lr1 + 16][c4 + 3] = vv2.w;
        __syncthreads();

        const int nnb = g << 4;
#pragma unroll
        for (int s = 0; s < 16; s++) {
            const int nn = nnb + s;
            float ka[4], vb[4];
#pragma unroll
            for (int i = 0; i < 4; i++) ka[i] = sk[d0 + i][nn];
#pragma unroll
            for (int j = 0; j < 4; j++) vb[j] = sv[e0 + j][nn];
#pragma unroll
            for (int i = 0; i < 4; i++)
#pragma unroll
                for (int j = 0; j < 4; j++) acc[i][j] += ka[i] * vb[j];
        }
        __syncthreads();
    }

    float* cp = g_ctx + (size_t)(b * NHEAD + h) * DHEAD * DHEAD;
#pragma unroll
    for (int i = 0; i < 4; i++)
#pragma unroll
        for (int j = 0; j < 4; j++)
            atomicAdd(&cp[(d0 + i) * DHEAD + e0 + j], acc[i][j]);
}

// =====================================================================
// Kernel 4 (fused): q-softmax + att + w_out GEMM (HMMA) + bias + LN.
// CTA = 256 out-ch x 64 tokens. 8 warps (4m x 2n), warp tile 64x32.
// SMEM map:
//   A planes (w_out hi/lo)  @0       2 x 65536 = 131072   (overlaid by stage later)
//   B planes (att hi/lo)    @131072  2 x 16384 = 32768
//   qs fp32 [128][68]       @163840  34816
//   ctx fp32 [4096]         @198656  16384
//   bias/gamma/beta [256]   @215040  3072
//   smean/srstd [64]        @218112  512
// total 218624
// =====================================================================
#define FIN_SMEM   218624
#define F_OFF_B    131072
#define F_OFF_QS   163840
#define F_OFF_CTX  198656
#define F_OFF_BIAS 215040
#define F_OFF_GAM  216064
#define F_OFF_BET  217088
#define F_OFF_MEAN 218112
#define F_OFF_STD  218368

__global__ __launch_bounds__(256, 1) void k_final2(const float* __restrict__ bias,
                                                   const float* __restrict__ gamma,
                                                   const float* __restrict__ beta,
                                                   float* __restrict__ out) {
    extern __shared__ __align__(1024) char smem[];
    const uint32_t sb = smem_u32(smem);
    const int b  = blockIdx.y;
    const int n0 = blockIdx.x * 64;
    const int tid = threadIdx.x, wid = tid >> 5, lane = tid & 31;
    const int warp_m = wid >> 1, warp_n = wid & 1;

    float* qs   = (float*)(smem + F_OFF_QS);    // [128][68]
    float* sctx = (float*)(smem + F_OFF_CTX);   // [4096]
    float* sbias = (float*)(smem + F_OFF_BIAS);
    float* sgam  = (float*)(smem + F_OFF_GAM);
    float* sbet  = (float*)(smem + F_OFF_BET);
    float* smean = (float*)(smem + F_OFF_MEAN);
    float* srstd = (float*)(smem + F_OFF_STD);

    // ---- 1. async copy of w_out planes into A ----
#pragma unroll
    for (int p = 0; p < 2; p++) {
        const char* srcb = (const char*)g_w2 + (size_t)p * 65536;
#pragma unroll
        for (int i = 0; i < 16; i++) {
            int u = tid + 256 * i;               // 0..4095 16B units
            int m = u >> 4, ks = u & 15;
            uint32_t dst = sb + p * 65536 + m * 256 + ((ks * 16) ^ ((m & 7) << 4));
            CP_ASYNC16(dst, srcb + (size_t)u * 16);
        }
    }
    CP_COMMIT();

    // ---- 2. load ctx, q tile, LN params ----
    for (int i = tid; i < 4096; i += 256) sctx[i] = g_ctx[b * 4096 + i];
    if (tid < 64) {
        sbias[tid]       = bias[tid];        sbias[tid + 64]  = bias[tid + 64];
        sbias[tid + 128] = bias[tid + 128];  sbias[tid + 192] = bias[tid + 192];
        sgam[tid]        = gamma[tid];       sgam[tid + 64]   = gamma[tid + 64];
        sgam[tid + 128]  = gamma[tid + 128]; sgam[tid + 192]  = gamma[tid + 192];
        sbet[tid]        = beta[tid];        sbet[tid + 64]   = beta[tid + 64];
        sbet[tid + 128]  = beta[tid + 128];  sbet[tid + 192]  = beta[tid + 192];
    }
#pragma unroll
    for (int i = 0; i < 8; i++) {
        int idx = tid + i * 256;                 // 0..2047 float4s (128 rows x 16)
        int r = idx >> 4, c4 = (idx & 15) << 2;
        float4 v = *(const float4*)&g_qkv[((size_t)b * OC3 + r) * NTOK + n0 + c4];
        *(float4*)&qs[r * 68 + c4] = v;
    }
    __syncthreads();

    // ---- 3. q softmax over d per (h, n): thread = h*64 + n ----
    {
        const int h = tid >> 6, n = tid & 63;
        float qv[32];
        float m = -1e30f;
#pragma unroll
        for (int d = 0; d < 32; d++) { qv[d] = qs[(h * 32 + d) * 68 + n]; m = fmaxf(m, qv[d]); }
        float s = 0.f;
#pragma unroll
        for (int d = 0; d < 32; d++) { qv[d] = __expf(qv[d] - m); s += qv[d]; }
        const float r = SCALE / s;
#pragma unroll
        for (int d = 0; d < 32; d++) qs[(h * 32 + d) * 68 + n] = qv[d] * r;
    }
    __syncthreads();

    // ---- 4. att[e, n] = sum_d ctx[h,d,e'] * qs[h*32+d][n]; write bf16 hi/lo B ----
    {
        const int e = tid >> 1, nh = tid & 1;
        const int h = e >> 5, ep = e & 31;
        float av[32];
#pragma unroll
        for (int j = 0; j < 32; j++) av[j] = 0.f;
        const float* cb = sctx + h * 1024 + ep;
        const float* qb = qs + (h * 32) * 68 + nh * 32;
#pragma unroll
        for (int d = 0; d < 32; d++) {
            const float cv = cb[d * 32];
#pragma unroll
            for (int j = 0; j < 32; j++) av[j] += cv * qb[d * 68 + j];
        }
        char* bhi = smem + F_OFF_B;
        char* blo = bhi + 16384;
#pragma unroll
        for (int t = 0; t < 16; t++) {
            __nv_bfloat16 h0, h1, l0, l1;
            bf16_split(av[2 * t],     h0, l0);
            bf16_split(av[2 * t + 1], h1, l1);
            uint32_t hv = (uint32_t)__bfloat16_as_ushort(h0) | ((uint32_t)__bfloat16_as_ushort(h1) << 16);
            uint32_t lv = (uint32_t)__bfloat16_as_ushort(l0) | ((uint32_t)__bfloat16_as_ushort(l1) << 16);
            uint32_t off = (uint32_t)e * 128 + (((uint32_t)(nh * 64 + 4 * t)) ^ (((uint32_t)e & 7) << 4));
            *(uint32_t*)(bhi + off) = hv;
            *(uint32_t*)(blo + off) = lv;
        }
    }

    CP_WAIT0();
    __syncthreads();

    // ---- 5. MMA: 3 terms x 8 k-steps, warp tile 64m x 32n ----
    float acc[4][4][4];
#pragma unroll
    for (int i = 0; i < 4; i++)
#pragma unroll
        for (int j = 0; j < 4; j++)
#pragma unroll
            for (int r = 0; r < 4; r++) acc[i][j][r] = 0.f;

    const int lm = lane & 15;
    const int khalf = (lane >> 4) << 3;

#pragma unroll
    for (int t3 = 0; t3 < 3; t3++) {
        const int pa = (t3 == 2) ? 1 : 0;
        const int pb = (t3 == 1) ? 1 : 0;
        const uint32_t abase = sb + pa * 65536;
        const uint32_t bbase = sb + F_OFF_B + pb * 16384;
#pragma unroll
        for (int ks = 0; ks < 8; ks++) {
            uint32_t ar[4][4];
#pragma unroll
            for (int im = 0; im < 4; im++) {
                uint32_t m_row = (uint32_t)(warp_m * 64 + im * 16 + lm);
                uint32_t k_off = (uint32_t)(ks * 16 + khalf);
                uint32_t addr = abase + m_row * 256 + ((k_off * 2) ^ ((m_row & 7) << 4));
                LDSM_X4(ar[im][0], ar[im][1], ar[im][2], ar[im][3], addr);
            }
            uint32_t br[2][4];
#pragma unroll
            for (int jn = 0; jn < 2; jn++) {
                uint32_t k_row = (uint32_t)(ks * 16 + lm);
                uint32_t n_off = (uint32_t)(warp_n * 32 + jn * 16 + khalf);
                uint32_t addr = bbase + k_row * 128 + ((n_off * 2) ^ ((k_row & 7) << 4));
                LDSM_X4_T(br[jn][0], br[jn][1], br[jn][2], br[jn][3], addr);
            }
#pragma unroll
            for (int im = 0; im < 4; im++) {
#pragma unroll
                for (int jn = 0; jn < 2; jn++) {
                    MMA_16816(acc[im][jn * 2 + 0], ar[im], br[jn][0], br[jn][1]);
                    MMA_16816(acc[im][jn * 2 + 1], ar[im], br[jn][2], br[jn][3]);
                }
            }
        }
    }
    __syncthreads();   // A region dead; reuse as stage

    // ---- 6. stage = acc + bias (stage[256][68] overlays A) ----
    float* stage = (float*)smem;
    {
        const int g = lane >> 2, tig = lane & 3;
#pragma unroll
        for (int im = 0; im < 4; im++) {
            const int row = warp_m * 64 + im * 16 + g;
            const float b0 = sbias[row], b1 = sbias[row + 8];
#pragma unroll
            for (int jn = 0; jn < 4; jn++) {
                const int col = warp_n * 32 + jn * 8 + tig * 2;
                *(float2*)&stage[row * 68 + col] =
                    make_float2(acc[im][jn][0] + b0, acc[im][jn][1] + b0);
                *(float2*)&stage[(row + 8) * 68 + col] =
                    make_float2(acc[im][jn][2] + b1, acc[im][jn][3] + b1);
            }
        }
    }
    __syncthreads();

    // ---- 7. LN stats: 4 threads per token ----
    {
        const int t = tid >> 2, part = tid & 3;
        float sum = 0.f, sq = 0.f;
#pragma unroll
        for (int jj = 0; jj < 64; jj++) {
            const float v = stage[(part + jj * 4) * 68 + t];
            sum += v; sq += v * v;
        }
        sum += __shfl_xor_sync(0xffffffffu, sum, 1);
        sq  += __shfl_xor_sync(0xffffffffu, sq, 1);
        sum += __shfl_xor_sync(0xffffffffu, sum, 2);
        sq  += __shfl_xor_sync(0xffffffffu, sq, 2);
        const float mean = sum * (1.f / 256.f);
        const float var  = sq * (1.f / 256.f) - mean * mean;
        if (part == 0) {
            smean[t] = mean;
            srstd[t] = rsqrtf(var + LN_EPS);
        }
    }
    __syncthreads();

    // ---- 8. normalized write-out ----
    float* outb = out + (size_t)b * CIN * NTOK + n0;
#pragma unroll
    for (int it = 0; it < 16; it++) {
        int idx = it * 256 + tid;
        int o = idx >> 4, q = (idx & 15) << 2;
        const float gm = sgam[o], bt = sbet[o];
        float4 v = *(float4*)&stage[o * 68 + q];
        v.x = (v.x - smean[q + 0]) * srstd[q + 0] * gm + bt;
        v.y = (v.y - smean[q + 1]) * srstd[q + 1] * gm + bt;
        v.z = (v.z - smean[q + 2]) * srstd[q + 2] * gm + bt;
        v.w = (v.w - smean[q + 3]) * srstd[q + 3] * gm + bt;
        *(float4*)&outb[(size_t)o * NTOK + q] = v;
    }
}

// =====================================================================
extern "C" void kernel_launch(void* const* d_in, const int* in_sizes, int n_in,
                              void* d_out, int out_size) {
    const float* x      = (const float*)d_in[0];
    const float* w_qkv  = (const float*)d_in[1];
    const float* w_out  = (const float*)d_in[2];
    const float* bias   = (const float*)d_in[3];
    const float* gamma  = (const float*)d_in[4];
    const float* beta   = (const float*)d_in[5];
    float* out = (float*)d_out;

    cudaFuncSetAttribute(k_qkv_mma, cudaFuncAttributeMaxDynamicSharedMemorySize,
                         QKV_SMEM);
    cudaFuncSetAttribute(k_final2, cudaFuncAttributeMaxDynamicSharedMemorySize,
                         FIN_SMEM);

    k_wconv<<<192, 512>>>(w_qkv);
    k_wconv2<<<64, 512>>>(w_out);
    k_qkv_mma<<<dim3(NTOK / 128, 3, BATCH), 256, QKV_SMEM>>>(x);
    k_zero_ctx<<<16, 1024>>>();
    k_kstats<<<512, 256>>>();
    k_context<<<dim3(16, NHEAD, BATCH), 256>>>();
    k_final2<<<dim3(NTOK / 64, BATCH), 256, FIN_SMEM>>>(bias, gamma, beta, out);
}